// round 2
// baseline (speedup 1.0000x reference)
#include <cuda_runtime.h>
#include <cstdint>
#include <math.h>

#define NN      100000
#define EE      1600000
#define DD      32
#define NUMC    1024
#define NBINS   65536
#define CAP     4096
#define SORTN   4096

// ---------------- scratch (static __device__, no allocs) ----------------
__device__ int   g_cnt[NN];
__device__ int   g_rowptr[NN + 1];
__device__ int   g_cursor[NN];
__device__ int   g_bsums[128];
__device__ unsigned int g_csr[EE];
__device__ float g_ord0[NN], g_ord1[NN], g_ord2[NN];
__device__ float g_embA[NN * DD], g_embB[NN * DD], g_esum[NN * DD];
__device__ float g_numA[NN], g_numB[NN], g_nsum[NN];
__device__ float g_gum[NN];
__device__ float g_scores[NN];
__device__ int   g_hist[NBINS];
__device__ int   g_pivotB;
__device__ unsigned long long g_cand[CAP];
__device__ int   g_candcnt;

// ---------------- threefry2x32 (exact JAX) ----------------
static __host__ __device__ inline void tf2x32(uint32_t k0, uint32_t k1,
                                              uint32_t x0, uint32_t x1,
                                              uint32_t& o0, uint32_t& o1) {
    uint32_t ks2 = k0 ^ k1 ^ 0x1BD11BDAu;
    x0 += k0; x1 += k1;
#define TF_R(r) { x0 += x1; x1 = (x1 << r) | (x1 >> (32 - r)); x1 ^= x0; }
    TF_R(13) TF_R(15) TF_R(26) TF_R(6)   x0 += k1;  x1 += ks2 + 1u;
    TF_R(17) TF_R(29) TF_R(16) TF_R(24)  x0 += ks2; x1 += k0 + 2u;
    TF_R(13) TF_R(15) TF_R(26) TF_R(6)   x0 += k0;  x1 += k1 + 3u;
    TF_R(17) TF_R(29) TF_R(16) TF_R(24)  x0 += k1;  x1 += ks2 + 4u;
    TF_R(13) TF_R(15) TF_R(26) TF_R(6)   x0 += ks2; x1 += k0 + 5u;
#undef TF_R
    o0 = x0; o1 = x1;
}

// partitionable-mode 32-bit random bits for element j: xor of the two outputs,
// counter = (hi=0, lo=j)
static __device__ inline uint32_t tf_bits(uint32_t k0, uint32_t k1, uint32_t j) {
    uint32_t o0, o1;
    tf2x32(k0, k1, 0u, j, o0, o1);
    return o0 ^ o1;
}

__device__ inline float u01(uint32_t b) {
    return __uint_as_float((b >> 9) | 0x3f800000u) - 1.0f;
}

__device__ inline float wsum(float v) {
    #pragma unroll
    for (int o = 16; o; o >>= 1) v += __shfl_xor_sync(0xffffffffu, v, o);
    return v;
}

// ---------------- kernels ----------------
__global__ void k_zero() {
    int i = blockIdx.x * blockDim.x + threadIdx.x;
    if (i < NN) g_cnt[i] = 0;
    if (i < NBINS) g_hist[i] = 0;
    if (i == 0) { g_candcnt = 0; g_pivotB = 0; }
}

__global__ void k_gumbel() {
    int j = blockIdx.x * blockDim.x + threadIdx.x;
    if (j >= NN) return;
    g_gum[j] = -logf(-logf(u01(tf_bits(0u, 7u, (uint32_t)j))));
}

__global__ void k_hist_rows(const int* __restrict__ rows) {
    int e = blockIdx.x * blockDim.x + threadIdx.x;
    if (e >= EE) return;
    atomicAdd(&g_cnt[rows[e]], 1);
}

__global__ void k_scanA() {
    __shared__ int s[1024];
    int t = threadIdx.x;
    int i = blockIdx.x * 1024 + t;
    int v = (i < NN) ? g_cnt[i] : 0;
    s[t] = v;
    __syncthreads();
    for (int off = 1; off < 1024; off <<= 1) {
        int x = (t >= off) ? s[t - off] : 0;
        __syncthreads();
        s[t] += x;
        __syncthreads();
    }
    if (i < NN) g_rowptr[i + 1] = s[t];
    if (t == 1023) g_bsums[blockIdx.x] = s[1023];
}

__global__ void k_scanB(int nb) {
    if (threadIdx.x == 0) {
        int run = 0;
        for (int b = 0; b < nb; b++) { int t = g_bsums[b]; g_bsums[b] = run; run += t; }
    }
}

__global__ void k_scanC() {
    int i = blockIdx.x * blockDim.x + threadIdx.x;
    if (i < NN) g_rowptr[i + 1] += g_bsums[i >> 10];
    if (i == 0) g_rowptr[0] = 0;
}

__global__ void k_cursor() {
    int i = blockIdx.x * blockDim.x + threadIdx.x;
    if (i < NN) g_cursor[i] = g_rowptr[i];
}

// scatter edges into CSR, computing the compounding dropout mask inline
// (exact JAX partitionable threefry; keys for fold_in(key(42), it) passed in)
__global__ void k_scatter(const int* __restrict__ rows, const int* __restrict__ cols,
                          uint32_t a0, uint32_t a1, uint32_t b0, uint32_t b1,
                          uint32_t c0, uint32_t c1) {
    int e = blockIdx.x * blockDim.x + threadIdx.x;
    if (e >= EE) return;

    uint32_t K0[3] = {a0, b0, c0}, K1[3] = {a1, b1, c1};
    const float P[3] = {0.5f, 0.25f, 0.125f};
    unsigned int m = 0;
    bool s = true;
    #pragma unroll
    for (int it = 0; it < 3; it++) {
        float u = u01(tf_bits(K0[it], K1[it], (uint32_t)e));
        bool k = floorf(u + P[it]) != 0.0f;
        s = s && k;
        if (s) m |= (1u << it);
    }

    int r = rows[e];
    unsigned int pk = (unsigned int)cols[e] | (m << 24);
    int p = atomicAdd(&g_cursor[r], 1);
    g_csr[p] = pk;
}

__global__ void k_sortcount() {
    int n = blockIdx.x * blockDim.x + threadIdx.x;
    if (n >= NN) return;
    int b = g_rowptr[n], e = g_rowptr[n + 1];
    int deg = e - b;
    int c1 = 0, c2 = 0;
    if (deg <= 96) {
        unsigned int loc[96];
        for (int i = 0; i < deg; i++) loc[i] = g_csr[b + i];
        for (int i = 1; i < deg; i++) {
            unsigned int v = loc[i]; int j = i - 1;
            while (j >= 0 && loc[j] > v) { loc[j + 1] = loc[j]; j--; }
            loc[j + 1] = v;
        }
        for (int i = 0; i < deg; i++) {
            unsigned m = loc[i] >> 24;
            c1 += (m & 1); c2 += (m >> 1) & 1;
            g_csr[b + i] = loc[i];
        }
    } else {
        for (int i = b + 1; i < e; i++) {
            unsigned int v = g_csr[i]; int j = i - 1;
            while (j >= b && g_csr[j] > v) { g_csr[j + 1] = g_csr[j]; j--; }
            g_csr[j + 1] = v;
        }
        for (int i = b; i < e; i++) {
            unsigned m = g_csr[i] >> 24;
            c1 += (m & 1); c2 += (m >> 1) & 1;
        }
    }
    g_ord0[n] = (float)deg;
    g_ord1[n] = (float)c1;
    g_ord2[n] = (float)c2;
    g_numA[n] = (float)deg;   // num0 = order0
    g_nsum[n] = (float)deg;   // running sum of num
}

__global__ void k_stage0(const float* __restrict__ emb) {
    int gw = (blockIdx.x * blockDim.x + threadIdx.x) >> 5;
    int lane = threadIdx.x & 31;
    if (gw >= NN) return;
    int b = g_rowptr[gw], e = g_rowptr[gw + 1];
    float acc = 0.f;
    for (int i = b; i < e; i++) {
        unsigned pk = g_csr[i];
        acc += emb[(pk & 0x00FFFFFFu) * DD + lane];
    }
    float self = emb[gw * DD + lane];
    float o = acc - self;
    g_embA[gw * DD + lane] = o;
    g_esum[gw * DD + lane] = o;
}

template <int S>
__global__ void k_stage() {
    const float* ep;  float* enx;
    const float* np;  float* nn;
    const float* ordp;
    if (S == 1)      { ep = g_embA; enx = g_embB; np = g_numA; nn = g_numB; ordp = g_ord0; }
    else if (S == 2) { ep = g_embB; enx = g_embA; np = g_numB; nn = g_numA; ordp = g_ord1; }
    else             { ep = g_embA; enx = g_embB; np = g_numA; nn = g_numB; ordp = g_ord2; }
    const unsigned mb = 1u << (24 + S - 1);

    int gw = (blockIdx.x * blockDim.x + threadIdx.x) >> 5;
    int lane = threadIdx.x & 31;
    if (gw >= NN) return;
    int b = g_rowptr[gw], e = g_rowptr[gw + 1];

    float acc = 0.f;
    for (int i = b; i < e; i++) {
        unsigned pk = g_csr[i];
        if (pk & mb) acc += ep[(pk & 0x00FFFFFFu) * DD + lane];
    }
    float na = 0.f;
    for (int i = b + lane; i < e; i += 32) {
        unsigned pk = g_csr[i];
        if (pk & mb) na += np[pk & 0x00FFFFFFu];
    }
    na = wsum(na);

    float self = ep[gw * DD + lane];
    float ov = ordp[gw];
    float o = acc - self - ov * self;
    enx[gw * DD + lane] = o;
    g_esum[gw * DD + lane] += o;
    if (lane == 0) {
        float nv = na - np[gw] - ov;
        nn[gw] = nv;
        g_nsum[gw] += nv;
    }
}

__global__ void k_score(const float* __restrict__ emb, float* outS) {
    int gw = (blockIdx.x * blockDim.x + threadIdx.x) >> 5;
    int lane = threadIdx.x & 31;
    if (gw >= NN) return;
    float ns = g_nsum[gw] + 1e-8f;
    float sd = g_esum[gw * DD + lane] / ns;
    float ed = emb[gw * DD + lane];
    float ss = wsum(sd * sd);
    float ee = wsum(ed * ed);
    float sn  = fmaxf(sqrtf(ss), 1e-12f);
    float en2 = fmaxf(sqrtf(ee), 1e-12f);
    float dot = wsum((sd / sn) * (ed / en2));
    if (lane == 0) {
        float sc = dot + g_gum[gw];
        g_scores[gw] = sc;
        if (outS) outS[gw] = sc;
        unsigned bits = __float_as_uint(sc);
        unsigned key = bits ^ ((bits & 0x80000000u) ? 0xFFFFFFFFu : 0x80000000u);
        atomicAdd(&g_hist[key >> 16], 1);
    }
}

__global__ void k_pivot() {
    __shared__ int ssum[1024];
    int t = threadIdx.x;
    int s = 0;
    for (int i = 0; i < 64; i++) s += g_hist[t * 64 + i];
    ssum[t] = s;
    __syncthreads();
    if (t == 0) {
        int run = 0, B = 0;
        for (int st = 1023; st >= 0; st--) {
            if (run + ssum[st] >= NUMC) {
                for (int i = 63; i >= 0; i--) {
                    run += g_hist[st * 64 + i];
                    if (run >= NUMC) { B = st * 64 + i; break; }
                }
                break;
            }
            run += ssum[st];
        }
        g_pivotB = B;
    }
}

__global__ void k_compact() {
    int n = blockIdx.x * blockDim.x + threadIdx.x;
    if (n >= NN) return;
    unsigned bits = __float_as_uint(g_scores[n]);
    unsigned key = bits ^ ((bits & 0x80000000u) ? 0xFFFFFFFFu : 0x80000000u);
    if ((int)(key >> 16) >= g_pivotB) {
        int p = atomicAdd(&g_candcnt, 1);
        if (p < CAP)
            g_cand[p] = ((unsigned long long)key << 32) |
                        (unsigned long long)(0xFFFFFFFFu - (unsigned)n);
    }
}

__global__ void k_sorttop(float* outC) {
    __shared__ unsigned long long s[SORTN];
    int t = threadIdx.x;
    int cnt = g_candcnt; if (cnt > CAP) cnt = CAP;
    for (int i = t; i < SORTN; i += 1024)
        s[i] = (i < cnt) ? g_cand[i] : 0ULL;
    __syncthreads();
    for (int k = 2; k <= SORTN; k <<= 1) {
        for (int j = k >> 1; j > 0; j >>= 1) {
            for (int i = t; i < SORTN; i += 1024) {
                int ixj = i ^ j;
                if (ixj > i) {
                    unsigned long long a = s[i], b = s[ixj];
                    bool desc = (i & k) == 0;   // final order: descending
                    bool sw = desc ? (a < b) : (a > b);
                    if (sw) { s[i] = b; s[ixj] = a; }
                }
            }
            __syncthreads();
        }
    }
    if (t < NUMC && outC)
        outC[t] = (float)(0xFFFFFFFFu - (unsigned)(s[t] & 0xFFFFFFFFull));
}

// ---------------- launch ----------------
extern "C" void kernel_launch(void* const* d_in, const int* in_sizes, int n_in,
                              void* d_out, int out_size) {
    const int* ei = (const int*)d_in[0];       // edge_index [2, E]
    const int* rows = ei;
    const int* cols = ei + EE;
    const float* emb = (const float*)d_in[2];  // embeds [N, 32]
    float* out = (float*)d_out;

    float* outS = nullptr; float* outC = nullptr;
    if (out_size >= NN + NUMC)      { outS = out; outC = out + NN; }
    else if (out_size == NUMC)      { outC = out; }
    else                            { outS = out; }

    // folded dropout keys: fold_in(key(42), i) = threefry_2x32((0,42), [0, i])
    // (fold_in is NOT gated by the partitionable flag -> original split scheme,
    //  which for a size-2 count is x0=[0], x1=[i], new key = (o0, o1))
    uint32_t dk0[3], dk1[3];
    for (uint32_t i = 0; i < 3; i++) tf2x32(0u, 42u, 0u, i, dk0[i], dk1[i]);

    const int T = 256;
    k_zero<<<(NN + T - 1) / T, T>>>();
    k_gumbel<<<(NN + T - 1) / T, T>>>();
    k_hist_rows<<<(EE + T - 1) / T, T>>>(rows);
    k_scanA<<<(NN + 1023) / 1024, 1024>>>();
    k_scanB<<<1, 32>>>((NN + 1023) / 1024);
    k_scanC<<<(NN + 1023) / 1024, 1024>>>();
    k_cursor<<<(NN + T - 1) / T, T>>>();
    k_scatter<<<(EE + T - 1) / T, T>>>(rows, cols,
                                       dk0[0], dk1[0], dk0[1], dk1[1], dk0[2], dk1[2]);
    k_sortcount<<<(NN + T - 1) / T, T>>>();

    const int WB = 12500; // NN warps / 8 warps per 256-thread block
    k_stage0<<<WB, 256>>>(emb);
    k_stage<1><<<WB, 256>>>();
    k_stage<2><<<WB, 256>>>();
    k_stage<3><<<WB, 256>>>();
    k_score<<<WB, 256>>>(emb, outS);
    k_pivot<<<1, 1024>>>();
    k_compact<<<(NN + T - 1) / T, T>>>();
    k_sorttop<<<1, 1024>>>(outC);
}

// round 4
// speedup vs baseline: 1.2683x; 1.2683x over previous
#include <cuda_runtime.h>
#include <cstdint>
#include <math.h>

#define NN      100000
#define EE      1600000
#define DD      32
#define NUMC    1024
#define NBINS   65536
#define CAP     4096
#define SORTN   4096

// ---------------- scratch (static __device__, no allocs) ----------------
__device__ int   g_cnt[NN];
__device__ int   g_rowptr[NN + 1];
__device__ int   g_cursor[NN];
__device__ int   g_bsums[128];
__device__ unsigned int g_csr[EE];
__device__ int   g_c1[NN], g_c2[NN], g_c3[NN];
__device__ float g_embA[NN * DD], g_embB[NN * DD], g_esum[NN * DD];
__device__ float g_numA[NN], g_numB[NN], g_nsum[NN];
__device__ float g_gum[NN];
__device__ float g_scores[NN];
__device__ int   g_hist[NBINS];
__device__ int   g_pivotB;
__device__ unsigned long long g_cand[CAP];
__device__ int   g_candcnt;

// ---------------- threefry2x32 (exact JAX) ----------------
static __host__ __device__ inline void tf2x32(uint32_t k0, uint32_t k1,
                                              uint32_t x0, uint32_t x1,
                                              uint32_t& o0, uint32_t& o1) {
    uint32_t ks2 = k0 ^ k1 ^ 0x1BD11BDAu;
    x0 += k0; x1 += k1;
#define TF_R(r) { x0 += x1; x1 = (x1 << r) | (x1 >> (32 - r)); x1 ^= x0; }
    TF_R(13) TF_R(15) TF_R(26) TF_R(6)   x0 += k1;  x1 += ks2 + 1u;
    TF_R(17) TF_R(29) TF_R(16) TF_R(24)  x0 += ks2; x1 += k0 + 2u;
    TF_R(13) TF_R(15) TF_R(26) TF_R(6)   x0 += k0;  x1 += k1 + 3u;
    TF_R(17) TF_R(29) TF_R(16) TF_R(24)  x0 += k1;  x1 += ks2 + 4u;
    TF_R(13) TF_R(15) TF_R(26) TF_R(6)   x0 += ks2; x1 += k0 + 5u;
#undef TF_R
    o0 = x0; o1 = x1;
}

// partitionable-mode 32-bit random bits for element j: xor of outputs, counter (0, j)
static __device__ inline uint32_t tf_bits(uint32_t k0, uint32_t k1, uint32_t j) {
    uint32_t o0, o1;
    tf2x32(k0, k1, 0u, j, o0, o1);
    return o0 ^ o1;
}

__device__ inline float u01(uint32_t b) {
    return __uint_as_float((b >> 9) | 0x3f800000u) - 1.0f;
}

__device__ inline float wsum(float v) {
    #pragma unroll
    for (int o = 16; o; o >>= 1) v += __shfl_xor_sync(0xffffffffu, v, o);
    return v;
}

// ---------------- kernels ----------------
__global__ void k_init() {
    int i = blockIdx.x * blockDim.x + threadIdx.x;
    if (i < NN) {
        g_cnt[i] = 0;
        g_gum[i] = -logf(-logf(u01(tf_bits(0u, 7u, (uint32_t)i))));
    }
    if (i < NBINS) g_hist[i] = 0;
    if (i == 0) { g_candcnt = 0; g_pivotB = 0; }
}

__global__ void k_hist_rows(const int* __restrict__ rows) {
    int e = blockIdx.x * blockDim.x + threadIdx.x;
    if (e >= EE) return;
    atomicAdd(&g_cnt[rows[e]], 1);
}

__global__ void k_scanA() {
    __shared__ int s[1024];
    int t = threadIdx.x;
    int i = blockIdx.x * 1024 + t;
    int v = (i < NN) ? g_cnt[i] : 0;
    s[t] = v;
    __syncthreads();
    for (int off = 1; off < 1024; off <<= 1) {
        int x = (t >= off) ? s[t - off] : 0;
        __syncthreads();
        s[t] += x;
        __syncthreads();
    }
    if (i < NN) g_rowptr[i + 1] = s[t];
    if (t == 1023) g_bsums[blockIdx.x] = s[1023];
}

__global__ void k_scanB(int nb) {
    if (threadIdx.x == 0) {
        int run = 0;
        for (int b = 0; b < nb; b++) { int t = g_bsums[b]; g_bsums[b] = run; run += t; }
    }
}

__global__ void k_scanC() {
    int i = blockIdx.x * blockDim.x + threadIdx.x;
    if (i < NN) {
        int v = g_rowptr[i + 1] + g_bsums[i >> 10];
        g_rowptr[i + 1] = v;
        if (i + 1 < NN) g_cursor[i + 1] = v;
    }
    if (i == 0) { g_rowptr[0] = 0; g_cursor[0] = 0; }
}

// scatter edges into CSR with inline compounding dropout mask
// sortkey = ((7-m)<<24) | col  -> ascending sort = mask-descending, col-ascending
__global__ void k_scatter(const int* __restrict__ rows, const int* __restrict__ cols,
                          uint32_t a0, uint32_t a1, uint32_t b0, uint32_t b1,
                          uint32_t c0, uint32_t c1) {
    int e = blockIdx.x * blockDim.x + threadIdx.x;
    if (e >= EE) return;

    uint32_t K0[3] = {a0, b0, c0}, K1[3] = {a1, b1, c1};
    const float P[3] = {0.5f, 0.25f, 0.125f};
    unsigned int m = 0;
    bool s = true;
    #pragma unroll
    for (int it = 0; it < 3; it++) {
        float u = u01(tf_bits(K0[it], K1[it], (uint32_t)e));
        bool k = floorf(u + P[it]) != 0.0f;
        s = s && k;
        if (s) m |= (1u << it);
    }

    int r = rows[e];
    unsigned int sk = ((7u - m) << 24) | (unsigned int)cols[e];
    int p = atomicAdd(&g_cursor[r], 1);
    g_csr[p] = sk;
}

// warp-per-row: register bitonic sort (asc) + mask-prefix counts via ballot
__global__ void k_sortrows() {
    const unsigned full = 0xffffffffu;
    int gw = (blockIdx.x * blockDim.x + threadIdx.x) >> 5;
    int lane = threadIdx.x & 31;
    if (gw >= NN) return;
    int b = g_rowptr[gw], e = g_rowptr[gw + 1];
    int d = e - b;
    const uint32_t PAD = 0xFFFFFFFFu;
    int c1 = 0, c2 = 0, c3 = 0;

    if (d <= 32) {
        uint32_t a = (lane < d) ? g_csr[b + lane] : PAD;
        c1 = __popc(__ballot_sync(full, a < 0x07000000u));
        c2 = __popc(__ballot_sync(full, a < 0x05000000u));
        c3 = __popc(__ballot_sync(full, a < 0x01000000u));
        #pragma unroll
        for (int k = 2; k <= 32; k <<= 1) {
            #pragma unroll
            for (int j = k >> 1; j > 0; j >>= 1) {
                uint32_t y = __shfl_xor_sync(full, a, j);
                bool asc = ((lane & k) == 0);
                bool low = ((lane & j) == 0);
                uint32_t mn = min(a, y), mx = max(a, y);
                a = (low == asc) ? mn : mx;
            }
        }
        if (lane < d) g_csr[b + lane] = a;
    } else if (d <= 64) {
        uint32_t x0 = (lane < d) ? g_csr[b + lane] : PAD;            // idx = lane
        uint32_t x1 = (lane + 32 < d) ? g_csr[b + lane + 32] : PAD;  // idx = lane+32
        c1 = __popc(__ballot_sync(full, x0 < 0x07000000u)) +
             __popc(__ballot_sync(full, x1 < 0x07000000u));
        c2 = __popc(__ballot_sync(full, x0 < 0x05000000u)) +
             __popc(__ballot_sync(full, x1 < 0x05000000u));
        c3 = __popc(__ballot_sync(full, x0 < 0x01000000u)) +
             __popc(__ballot_sync(full, x1 < 0x01000000u));
        #pragma unroll
        for (int k = 2; k <= 64; k <<= 1) {
            #pragma unroll
            for (int j = k >> 1; j > 0; j >>= 1) {
                if (j == 32) {  // only k==64: asc for all
                    uint32_t mn = min(x0, x1), mx = max(x0, x1);
                    x0 = mn; x1 = mx;
                } else {
                    bool asc0 = ((lane & k) == 0);
                    bool asc1 = (((lane + 32) & k) == 0);
                    bool low = ((lane & j) == 0);
                    uint32_t y0 = __shfl_xor_sync(full, x0, j);
                    uint32_t y1 = __shfl_xor_sync(full, x1, j);
                    uint32_t mn0 = min(x0, y0), mx0 = max(x0, y0);
                    uint32_t mn1 = min(x1, y1), mx1 = max(x1, y1);
                    x0 = (low == asc0) ? mn0 : mx0;
                    x1 = (low == asc1) ? mn1 : mx1;
                }
            }
        }
        if (lane < d) g_csr[b + lane] = x0;
        if (lane + 32 < d) g_csr[b + lane + 32] = x1;
    } else {
        if (lane == 0) {
            for (int i = b + 1; i < e; i++) {
                unsigned int v = g_csr[i]; int j = i - 1;
                while (j >= b && g_csr[j] > v) { g_csr[j + 1] = g_csr[j]; j--; }
                g_csr[j + 1] = v;
            }
            for (int i = b; i < e; i++) {
                uint32_t t = g_csr[i] >> 24;
                c1 += (t < 7); c2 += (t < 5); c3 += (t < 1);
            }
        }
    }
    if (lane == 0) {
        g_c1[gw] = c1; g_c2[gw] = c2; g_c3[gw] = c3;
        g_numA[gw] = (float)d;   // num0 = order0 = degree
        g_nsum[gw] = (float)d;
    }
}

__global__ void k_stage0(const float* __restrict__ emb) {
    int gw = (blockIdx.x * blockDim.x + threadIdx.x) >> 5;
    int lane = threadIdx.x & 31;
    if (gw >= NN) return;
    int b = g_rowptr[gw], e = g_rowptr[gw + 1];
    float acc = 0.f;
    for (int i = b; i < e; i++)
        acc += emb[(g_csr[i] & 0x00FFFFFFu) * DD + lane];
    float self = emb[gw * DD + lane];
    float o = acc - self;
    g_embA[gw * DD + lane] = o;
    g_esum[gw * DD + lane] = o;
}

template <int S>
__global__ void k_stage() {
    const float* ep;  float* enx;
    const float* np;  float* nn;
    const int* cb;    const int* cprev;
    if (S == 1)      { ep = g_embA; enx = g_embB; np = g_numA; nn = g_numB; cb = g_c1; cprev = nullptr; }
    else if (S == 2) { ep = g_embB; enx = g_embA; np = g_numB; nn = g_numA; cb = g_c2; cprev = g_c1; }
    else             { ep = g_embA; enx = g_embB; np = g_numA; nn = g_numB; cb = g_c3; cprev = g_c2; }

    int gw = (blockIdx.x * blockDim.x + threadIdx.x) >> 5;
    int lane = threadIdx.x & 31;
    if (gw >= NN) return;
    int b = g_rowptr[gw];
    int cnt = cb[gw];
    float ov = (S == 1) ? (float)(g_rowptr[gw + 1] - b) : (float)cprev[gw];

    float acc = 0.f;
    for (int i = b; i < b + cnt; i++)
        acc += ep[(g_csr[i] & 0x00FFFFFFu) * DD + lane];

    float na = 0.f;
    for (int i = b + lane; i < b + cnt; i += 32)
        na += np[g_csr[i] & 0x00FFFFFFu];
    na = wsum(na);

    float self = ep[gw * DD + lane];
    float o = acc - self - ov * self;
    enx[gw * DD + lane] = o;
    g_esum[gw * DD + lane] += o;
    if (lane == 0) {
        float nv = na - np[gw] - ov;
        nn[gw] = nv;
        g_nsum[gw] += nv;
    }
}

__global__ void k_score(const float* __restrict__ emb, float* outS) {
    int gw = (blockIdx.x * blockDim.x + threadIdx.x) >> 5;
    int lane = threadIdx.x & 31;
    if (gw >= NN) return;
    float ns = g_nsum[gw] + 1e-8f;
    float sd = g_esum[gw * DD + lane] / ns;
    float ed = emb[gw * DD + lane];
    float ss = wsum(sd * sd);
    float ee = wsum(ed * ed);
    float sn  = fmaxf(sqrtf(ss), 1e-12f);
    float en2 = fmaxf(sqrtf(ee), 1e-12f);
    float dot = wsum((sd / sn) * (ed / en2));
    if (lane == 0) {
        float sc = dot + g_gum[gw];
        g_scores[gw] = sc;
        if (outS) outS[gw] = sc;
        unsigned bits = __float_as_uint(sc);
        unsigned key = bits ^ ((bits & 0x80000000u) ? 0xFFFFFFFFu : 0x80000000u);
        atomicAdd(&g_hist[key >> 16], 1);
    }
}

__global__ void k_pivot() {
    __shared__ int ssum[1024];
    int t = threadIdx.x;
    int s = 0;
    for (int i = 0; i < 64; i++) s += g_hist[t * 64 + i];
    ssum[t] = s;
    __syncthreads();
    if (t == 0) {
        int run = 0, B = 0;
        for (int st = 1023; st >= 0; st--) {
            if (run + ssum[st] >= NUMC) {
                for (int i = 63; i >= 0; i--) {
                    run += g_hist[st * 64 + i];
                    if (run >= NUMC) { B = st * 64 + i; break; }
                }
                break;
            }
            run += ssum[st];
        }
        g_pivotB = B;
    }
}

__global__ void k_compact() {
    int n = blockIdx.x * blockDim.x + threadIdx.x;
    if (n >= NN) return;
    unsigned bits = __float_as_uint(g_scores[n]);
    unsigned key = bits ^ ((bits & 0x80000000u) ? 0xFFFFFFFFu : 0x80000000u);
    if ((int)(key >> 16) >= g_pivotB) {
        int p = atomicAdd(&g_candcnt, 1);
        if (p < CAP)
            g_cand[p] = ((unsigned long long)key << 32) |
                        (unsigned long long)(0xFFFFFFFFu - (unsigned)n);
    }
}

__global__ void k_sorttop(float* outC) {
    __shared__ unsigned long long s[SORTN];
    int t = threadIdx.x;
    int cnt = g_candcnt; if (cnt > CAP) cnt = CAP;
    for (int i = t; i < SORTN; i += 1024)
        s[i] = (i < cnt) ? g_cand[i] : 0ULL;
    __syncthreads();
    for (int k = 2; k <= SORTN; k <<= 1) {
        for (int j = k >> 1; j > 0; j >>= 1) {
            for (int i = t; i < SORTN; i += 1024) {
                int ixj = i ^ j;
                if (ixj > i) {
                    unsigned long long a = s[i], b = s[ixj];
                    bool desc = (i & k) == 0;   // final order: descending
                    bool sw = desc ? (a < b) : (a > b);
                    if (sw) { s[i] = b; s[ixj] = a; }
                }
            }
            __syncthreads();
        }
    }
    if (t < NUMC && outC)
        outC[t] = (float)(0xFFFFFFFFu - (unsigned)(s[t] & 0xFFFFFFFFull));
}

// ---------------- launch ----------------
extern "C" void kernel_launch(void* const* d_in, const int* in_sizes, int n_in,
                              void* d_out, int out_size) {
    const int* ei = (const int*)d_in[0];       // edge_index [2, E]
    const int* rows = ei;
    const int* cols = ei + EE;
    const float* emb = (const float*)d_in[2];  // embeds [N, 32]
    float* out = (float*)d_out;

    float* outS = nullptr; float* outC = nullptr;
    if (out_size >= NN + NUMC)      { outS = out; outC = out + NN; }
    else if (out_size == NUMC)      { outC = out; }
    else                            { outS = out; }

    // fold_in(key(42), i) = threefry_2x32((0,42), [0, i]) -> new key (o0, o1)
    uint32_t dk0[3], dk1[3];
    for (uint32_t i = 0; i < 3; i++) tf2x32(0u, 42u, 0u, i, dk0[i], dk1[i]);

    const int T = 256;
    k_init<<<(NN + T - 1) / T, T>>>();
    k_hist_rows<<<(EE + T - 1) / T, T>>>(rows);
    k_scanA<<<(NN + 1023) / 1024, 1024>>>();
    k_scanB<<<1, 32>>>((NN + 1023) / 1024);
    k_scanC<<<(NN + 1023) / 1024, 1024>>>();
    k_scatter<<<(EE + T - 1) / T, T>>>(rows, cols,
                                       dk0[0], dk1[0], dk0[1], dk1[1], dk0[2], dk1[2]);
    const int WB = 12500; // 100000 warps / 8 warps per 256-thread block
    k_sortrows<<<WB, 256>>>();
    k_stage0<<<WB, 256>>>(emb);
    k_stage<1><<<WB, 256>>>();
    k_stage<2><<<WB, 256>>>();
    k_stage<3><<<WB, 256>>>();
    k_score<<<WB, 256>>>(emb, outS);
    k_pivot<<<1, 1024>>>();
    k_compact<<<(NN + T - 1) / T, T>>>();
    k_sorttop<<<1, 1024>>>(outC);
}